// round 13
// baseline (speedup 1.0000x reference)
#include <cuda_runtime.h>
#include <cuda_bf16.h>

#define TABLE_SCALE 1024.0f   // 2^10
#define TABLE_SIZE  4096
#define TABLE_MAX   (TABLE_SIZE - 1)
#define UNROLL 4
#define THREADS 256
#define CHUNK_F4 (THREADS * UNROLL)        // 1024 float4 = 16 KB sub-chunk
#define SUBCHUNKS 4                        // 4 x 16 KB = 64 KB per ticket
#define TICKET_F4 (CHUNK_F4 * SUBCHUNKS)
#define NUM_CTAS (152 * 8)                 // one resident wave on GB300

// Self-resetting scheduler (R12): no init kernel. Stolen ticket id =
// ctas + g_ticket++. Last CTA to finish resets counters so every launch
// (correctness + each graph replay) sees g_ticket == g_done == 0.
__device__ unsigned int g_ticket = 0;
__device__ unsigned int g_done   = 0;

__device__ __forceinline__ int table_idx(float x) {
    int c = (int)(fabsf(x) * TABLE_SCALE);   // truncation toward zero
    return min(c, TABLE_MAX);
}

// Persistent work-stealing (latency-hidden ticket) + barrier amortization:
// one ticket covers 4 x 16 KB sub-chunks processed back-to-back with NO
// synchronization between them (addresses derive from the ticket), so the
// two __syncthreads run once per 64 KB instead of per 16 KB — cutting
// barrier overhead from ~5-9% of runtime to ~2%. Core per-sub-chunk shape
// is the R9 winner: U=4 front-batched .cs loads, smem table gathers,
// .cs stores.
__global__ void __launch_bounds__(THREADS) SecGELU_kernel(
    const float4* __restrict__ x,
    const float* __restrict__ table,
    float4* __restrict__ out,
    int n4, unsigned int num_tickets, unsigned int ctas)
{
    __shared__ float table_s[TABLE_SIZE];
    __shared__ unsigned int s_next;

    {   // cooperative fill: 4096 floats = 1024 float4, 4 per thread
        const float4* t4 = (const float4*)table;
        float4* s4 = (float4*)table_s;
        #pragma unroll
        for (int k = 0; k < TABLE_SIZE / 4 / THREADS; k++)
            s4[threadIdx.x + k * THREADS] = t4[threadIdx.x + k * THREADS];
    }
    __syncthreads();

    unsigned int ticket = blockIdx.x;

    while (ticket < num_tickets) {
        // Prefetch next ticket; ~318cyc atomic hides under ~4400cyc of work.
        if (threadIdx.x == 0)
            s_next = ctas + atomicAdd(&g_ticket, 1u);

        int tbase = (int)(ticket * TICKET_F4);

        #pragma unroll 1
        for (int s = 0; s < SUBCHUNKS; s++) {
            int base = tbase + s * CHUNK_F4 + threadIdx.x;

            if (base + (UNROLL - 1) * THREADS < n4) {
                float4 v[UNROLL];
                #pragma unroll
                for (int k = 0; k < UNROLL; k++)
                    v[k] = __ldcs(x + base + k * THREADS);   // front-batched

                float t[UNROLL][4];
                #pragma unroll
                for (int k = 0; k < UNROLL; k++) {
                    t[k][0] = table_s[table_idx(v[k].x)];
                    t[k][1] = table_s[table_idx(v[k].y)];
                    t[k][2] = table_s[table_idx(v[k].z)];
                    t[k][3] = table_s[table_idx(v[k].w)];
                }

                #pragma unroll
                for (int k = 0; k < UNROLL; k++) {
                    float4 r;
                    r.x = (v[k].x >= 0.0f ? v[k].x : 0.0f) - t[k][0];
                    r.y = (v[k].y >= 0.0f ? v[k].y : 0.0f) - t[k][1];
                    r.z = (v[k].z >= 0.0f ? v[k].z : 0.0f) - t[k][2];
                    r.w = (v[k].w >= 0.0f ? v[k].w : 0.0f) - t[k][3];
                    __stcs(out + base + k * THREADS, r);
                }
            } else {
                #pragma unroll
                for (int k = 0; k < UNROLL; k++) {
                    int i = base + k * THREADS;
                    if (i < n4) {
                        float4 v = __ldcs(x + i);
                        float4 r;
                        r.x = (v.x >= 0.0f ? v.x : 0.0f) - table_s[table_idx(v.x)];
                        r.y = (v.y >= 0.0f ? v.y : 0.0f) - table_s[table_idx(v.y)];
                        r.z = (v.z >= 0.0f ? v.z : 0.0f) - table_s[table_idx(v.z)];
                        r.w = (v.w >= 0.0f ? v.w : 0.0f) - table_s[table_idx(v.w)];
                        __stcs(out + i, r);
                    }
                }
            }
        }

        __syncthreads();          // s_next written + chunk work issued
        ticket = s_next;
        __syncthreads();          // all read s_next before tid0 rewrites it
    }

    // Self-reset: last CTA restores scheduler state for the next launch.
    if (threadIdx.x == 0) {
        unsigned int d = atomicAdd(&g_done, 1u);
        if (d == ctas - 1) {
            atomicExch(&g_ticket, 0u);
            atomicExch(&g_done, 0u);
        }
    }
}

// Tail handler for n not divisible by 4 (not needed for 2^26, but safe).
__global__ void SecGELU_tail(
    const float* __restrict__ x,
    const float* __restrict__ table,
    float* __restrict__ out,
    int start, int n)
{
    int i = start + blockIdx.x * blockDim.x + threadIdx.x;
    if (i >= n) return;
    float v = x[i];
    out[i] = (v >= 0.0f ? v : 0.0f) - __ldg(table + table_idx(v));
}

extern "C" void kernel_launch(void* const* d_in, const int* in_sizes, int n_in,
                              void* d_out, int out_size) {
    const float* x     = (const float*)d_in[0];
    const float* table = (const float*)d_in[1];
    float* out = (float*)d_out;

    int n  = in_sizes[0];
    int n4 = n >> 2;

    if (n4 > 0) {
        unsigned int num_tickets = (unsigned int)((n4 + TICKET_F4 - 1) / TICKET_F4);
        unsigned int ctas = num_tickets < NUM_CTAS ? num_tickets : NUM_CTAS;

        SecGELU_kernel<<<ctas, THREADS>>>(
            (const float4*)x, table, (float4*)out, n4, num_tickets, ctas);
    }
    int rem = n - (n4 << 2);
    if (rem > 0) {
        SecGELU_tail<<<1, 32>>>(x, table, out, n4 << 2, n);
    }
}

// round 14
// speedup vs baseline: 1.0995x; 1.0995x over previous
#include <cuda_runtime.h>
#include <cuda_bf16.h>

#define TABLE_SCALE 1024.0f   // 2^10
#define TABLE_SIZE  4096
#define TABLE_MAX   (TABLE_SIZE - 1)
#define UNROLL 4
#define THREADS 256

__device__ __forceinline__ int table_idx(float x) {
    int c = (int)(fabsf(x) * TABLE_SCALE);   // truncation toward zero
    return min(c, TABLE_MAX);
}

// Final configuration (R9, empirical optimum over 13 measured variants):
//  - flat grid, one 16 KB tile per CTA, single kernel launch (lowest graph
//    overhead — every persistent/scheduler variant cost more wallclock)
//  - U=4 front-batched independent LDG.128 .cs loads (MLP_p1=4 hides DRAM
//    latency; U=8 measured neutral, .lu/.wb measured neutral/worse)
//  - table gathers from shared memory (unloads L1tex sector-replay pressure
//    from the queue shared with the streaming loads: +2 µs vs __ldg gathers)
//  - .cs streaming stores (beat .wb by ~1.4 µs: write lines shouldn't
//    linger in L2)
// Plateau at ~78% DRAM = mixed R/W HBM turnaround ceiling; no on-chip pipe
// saturates.
__global__ void __launch_bounds__(THREADS) SecGELU_kernel(
    const float4* __restrict__ x,
    const float* __restrict__ table,
    float4* __restrict__ out,
    int n4)
{
    __shared__ float table_s[TABLE_SIZE];

    {   // cooperative fill: 4096 floats = 1024 float4, 4 per thread
        const float4* t4 = (const float4*)table;
        float4* s4 = (float4*)table_s;
        #pragma unroll
        for (int k = 0; k < TABLE_SIZE / 4 / THREADS; k++)
            s4[threadIdx.x + k * THREADS] = t4[threadIdx.x + k * THREADS];
    }
    __syncthreads();

    int base = blockIdx.x * (THREADS * UNROLL) + threadIdx.x;

    if (base + (UNROLL - 1) * THREADS < n4) {
        float4 v[UNROLL];
        #pragma unroll
        for (int k = 0; k < UNROLL; k++)
            v[k] = __ldcs(x + base + k * THREADS);   // front-batched, independent

        float t[UNROLL][4];
        #pragma unroll
        for (int k = 0; k < UNROLL; k++) {
            t[k][0] = table_s[table_idx(v[k].x)];
            t[k][1] = table_s[table_idx(v[k].y)];
            t[k][2] = table_s[table_idx(v[k].z)];
            t[k][3] = table_s[table_idx(v[k].w)];
        }

        #pragma unroll
        for (int k = 0; k < UNROLL; k++) {
            float4 r;
            r.x = (v[k].x >= 0.0f ? v[k].x : 0.0f) - t[k][0];
            r.y = (v[k].y >= 0.0f ? v[k].y : 0.0f) - t[k][1];
            r.z = (v[k].z >= 0.0f ? v[k].z : 0.0f) - t[k][2];
            r.w = (v[k].w >= 0.0f ? v[k].w : 0.0f) - t[k][3];
            __stcs(out + base + k * THREADS, r);
        }
    } else {
        #pragma unroll
        for (int k = 0; k < UNROLL; k++) {
            int i = base + k * THREADS;
            if (i < n4) {
                float4 v = __ldcs(x + i);
                float4 r;
                r.x = (v.x >= 0.0f ? v.x : 0.0f) - table_s[table_idx(v.x)];
                r.y = (v.y >= 0.0f ? v.y : 0.0f) - table_s[table_idx(v.y)];
                r.z = (v.z >= 0.0f ? v.z : 0.0f) - table_s[table_idx(v.z)];
                r.w = (v.w >= 0.0f ? v.w : 0.0f) - table_s[table_idx(v.w)];
                __stcs(out + i, r);
            }
        }
    }
}

// Tail handler for n not divisible by 4 (not needed for 2^26, but safe).
__global__ void SecGELU_tail(
    const float* __restrict__ x,
    const float* __restrict__ table,
    float* __restrict__ out,
    int start, int n)
{
    int i = start + blockIdx.x * blockDim.x + threadIdx.x;
    if (i >= n) return;
    float v = x[i];
    out[i] = (v >= 0.0f ? v : 0.0f) - __ldg(table + table_idx(v));
}

extern "C" void kernel_launch(void* const* d_in, const int* in_sizes, int n_in,
                              void* d_out, int out_size) {
    const float* x     = (const float*)d_in[0];
    const float* table = (const float*)d_in[1];
    float* out = (float*)d_out;

    int n  = in_sizes[0];
    int n4 = n >> 2;

    if (n4 > 0) {
        int per_block = THREADS * UNROLL;
        int blocks = (n4 + per_block - 1) / per_block;
        SecGELU_kernel<<<blocks, THREADS>>>(
            (const float4*)x, table, (float4*)out, n4);
    }
    int rem = n - (n4 << 2);
    if (rem > 0) {
        SecGELU_tail<<<1, 32>>>(x, table, out, n4 << 2, n);
    }
}